// round 1
// baseline (speedup 1.0000x reference)
#include <cuda_runtime.h>
#include <cuda_bf16.h>
#include <cstdint>

// Problem constants
#define B_   32
#define CH_  512
#define N_   1024      // H*W = 32*32
#define D_   64        // head dim
#define P_   8         // heads
#define BP_  256       // B*P
#define O3_  1536      // 3*CH

// Scratch: q, k' (=k + rel-pos), v in [b, p, n, d] layout. 64 MB each.
__device__ float g_q[(size_t)BP_ * N_ * D_];
__device__ float g_k[(size_t)BP_ * N_ * D_];
__device__ float g_v[(size_t)BP_ * N_ * D_];

// ---------------------------------------------------------------------------
// Kernel 1: QKV projection GEMM (per batch: W[1536,512] @ X[512,1024]),
// scattered directly into q/k/v head layout; rel-pos folded into k.
// Tile: 64 (o) x 64 (nn) per block, k-chunks of 32. 256 threads, 4x4 microtile.
// ---------------------------------------------------------------------------
__global__ __launch_bounds__(256) void qkv_kernel(
    const float* __restrict__ x,      // [B, C, 1024]
    const float* __restrict__ w,      // [1536, 512]
    const float* __restrict__ h_pos,  // [32, 1, 512]
    const float* __restrict__ w_pos)  // [1, 32, 512]
{
    __shared__ float Ws[32][64];  // [c_local][o_local]  (transposed)
    __shared__ float Xs[32][64];  // [c_local][nn_local]

    const int tid = threadIdx.x;
    const int tx = tid & 15;      // o-dim
    const int ty = tid >> 4;      // nn-dim
    const int o0 = blockIdx.x * 64;
    const int n0 = blockIdx.y * 64;
    const int b  = blockIdx.z;

    float acc[4][4];
#pragma unroll
    for (int i = 0; i < 4; i++)
#pragma unroll
        for (int j = 0; j < 4; j++) acc[i][j] = 0.f;

    const size_t xbase = (size_t)b * CH_ * N_;

    for (int t = 0; t < 16; t++) {
        const int c0 = t * 32;
        // Load W tile (64 o x 32 c), store transposed
        {
            const int r  = tid >> 3;         // 0..31
            const int cc = (tid & 7) * 4;    // 0..28
#pragma unroll
            for (int rr = 0; rr < 2; rr++) {
                const int oo = r + rr * 32;
                float4 wv = *(const float4*)&w[(size_t)(o0 + oo) * CH_ + c0 + cc];
                Ws[cc + 0][oo] = wv.x;
                Ws[cc + 1][oo] = wv.y;
                Ws[cc + 2][oo] = wv.z;
                Ws[cc + 3][oo] = wv.w;
            }
        }
        // Load X tile (32 c x 64 nn)
        {
            const int xr = tid >> 4;         // 0..15
            const int xc = (tid & 15) * 4;   // 0..60
#pragma unroll
            for (int rr = 0; rr < 2; rr++) {
                const int ccl = xr + rr * 16;
                *(float4*)&Xs[ccl][xc] =
                    *(const float4*)&x[xbase + (size_t)(c0 + ccl) * N_ + n0 + xc];
            }
        }
        __syncthreads();

#pragma unroll
        for (int kk = 0; kk < 32; kk++) {
            float4 a  = *(const float4*)&Ws[kk][tx * 4];
            float4 bb = *(const float4*)&Xs[kk][ty * 4];
            acc[0][0] += a.x * bb.x; acc[0][1] += a.x * bb.y;
            acc[0][2] += a.x * bb.z; acc[0][3] += a.x * bb.w;
            acc[1][0] += a.y * bb.x; acc[1][1] += a.y * bb.y;
            acc[1][2] += a.y * bb.z; acc[1][3] += a.y * bb.w;
            acc[2][0] += a.z * bb.x; acc[2][1] += a.z * bb.y;
            acc[2][2] += a.z * bb.z; acc[2][3] += a.z * bb.w;
            acc[3][0] += a.w * bb.x; acc[3][1] += a.w * bb.y;
            acc[3][2] += a.w * bb.z; acc[3][3] += a.w * bb.w;
        }
        __syncthreads();
    }

    // Epilogue: scatter into q/k/v head layout; fold rel-pos into k.
    const int o  = o0 + tx * 4;        // 4 consecutive o, same s/p (64-aligned tiles)
    const int s  = o >> 9;             // 0=q, 1=k, 2=v
    const int ch = o & 511;            // channel index p*64+dd
    const int p  = ch >> 6;
    const int dd = ch & 63;
    float* dst = (s == 0) ? g_q : (s == 1) ? g_k : g_v;

#pragma unroll
    for (int j = 0; j < 4; j++) {
        const int nn = n0 + ty * 4 + j;
        float4 v4;
        v4.x = acc[0][j]; v4.y = acc[1][j]; v4.z = acc[2][j]; v4.w = acc[3][j];
        if (s == 1) {
            const int hh = nn >> 5, ww = nn & 31;
            v4.x += h_pos[hh * CH_ + ch + 0] + w_pos[ww * CH_ + ch + 0];
            v4.y += h_pos[hh * CH_ + ch + 1] + w_pos[ww * CH_ + ch + 1];
            v4.z += h_pos[hh * CH_ + ch + 2] + w_pos[ww * CH_ + ch + 2];
            v4.w += h_pos[hh * CH_ + ch + 3] + w_pos[ww * CH_ + ch + 3];
        }
        const size_t idx = ((size_t)(b * P_ + p) * N_ + nn) * D_ + dd;
        *(float4*)&dst[idx] = v4;
    }
}

// ---------------------------------------------------------------------------
// Kernel 2: flash attention, fp32. One thread = one query row.
// Block: 128 threads = 128 query rows of one (b,p). K/V tiles of 32 rows in
// smem; q + accumulator live in registers; online softmax; fused transpose
// of the output back to [B, C, H, W].
// ---------------------------------------------------------------------------
__global__ __launch_bounds__(128) void attn_kernel(float* __restrict__ out)
{
    __shared__ float ks[32 * D_];  // 8 KB
    __shared__ float vs[32 * D_];  // 8 KB

    const int tid  = threadIdx.x;
    const int bp   = blockIdx.y;           // 0..255
    const int row  = blockIdx.x * 128 + tid;

    // Load q row into registers
    float q[D_], acc[D_];
    {
        const float4* qp = (const float4*)(g_q + ((size_t)bp * N_ + row) * D_);
#pragma unroll
        for (int d4 = 0; d4 < 16; d4++) {
            float4 t = qp[d4];
            q[d4 * 4 + 0] = t.x; q[d4 * 4 + 1] = t.y;
            q[d4 * 4 + 2] = t.z; q[d4 * 4 + 3] = t.w;
            acc[d4 * 4 + 0] = 0.f; acc[d4 * 4 + 1] = 0.f;
            acc[d4 * 4 + 2] = 0.f; acc[d4 * 4 + 3] = 0.f;
        }
    }

    float mrun = -1e30f;
    float lrun = 0.f;

    for (int mt = 0; mt < 32; mt++) {       // 32 tiles of 32 keys
        __syncthreads();
        {
            const float4* kg = (const float4*)(g_k + ((size_t)bp * N_ + mt * 32) * D_);
            const float4* vg = (const float4*)(g_v + ((size_t)bp * N_ + mt * 32) * D_);
            float4* k4 = (float4*)ks;
            float4* v4 = (float4*)vs;
#pragma unroll
            for (int r = 0; r < 4; r++) {
                k4[tid + r * 128] = kg[tid + r * 128];
                v4[tid + r * 128] = vg[tid + r * 128];
            }
        }
        __syncthreads();

        // scores for this tile
        float s[32];
#pragma unroll
        for (int mm = 0; mm < 32; mm++) {
            const float4* krow = (const float4*)(ks + mm * D_);
            float a = 0.f;
#pragma unroll
            for (int d4 = 0; d4 < 16; d4++) {
                float4 kv = krow[d4];
                a += q[d4 * 4 + 0] * kv.x;
                a += q[d4 * 4 + 1] * kv.y;
                a += q[d4 * 4 + 2] * kv.z;
                a += q[d4 * 4 + 3] * kv.w;
            }
            s[mm] = a;
        }

        // online softmax update
        float tmax = mrun;
#pragma unroll
        for (int mm = 0; mm < 32; mm++) tmax = fmaxf(tmax, s[mm]);
        const float alpha = __expf(mrun - tmax);
        mrun = tmax;
        lrun *= alpha;
#pragma unroll
        for (int dd = 0; dd < D_; dd++) acc[dd] *= alpha;

#pragma unroll
        for (int mm = 0; mm < 32; mm++) {
            const float pm = __expf(s[mm] - mrun);
            lrun += pm;
            const float4* vrow = (const float4*)(vs + mm * D_);
#pragma unroll
            for (int d4 = 0; d4 < 16; d4++) {
                float4 vv = vrow[d4];
                acc[d4 * 4 + 0] += pm * vv.x;
                acc[d4 * 4 + 1] += pm * vv.y;
                acc[d4 * 4 + 2] += pm * vv.z;
                acc[d4 * 4 + 3] += pm * vv.w;
            }
        }
    }

    // write out: out[b][p*64+dd][nn], coalesced across threads (nn = consecutive)
    const float linv = 1.0f / lrun;
    const int b = bp >> 3, p = bp & 7;
    float* ob = out + ((size_t)b * CH_ + p * D_) * N_ + row;
#pragma unroll
    for (int dd = 0; dd < D_; dd++) {
        ob[(size_t)dd * N_] = acc[dd] * linv;
    }
}

extern "C" void kernel_launch(void* const* d_in, const int* in_sizes, int n_in,
                              void* d_out, int out_size)
{
    const float* x     = (const float*)d_in[0];
    const float* qkv_w = (const float*)d_in[1];
    const float* h_pos = (const float*)d_in[2];
    const float* w_pos = (const float*)d_in[3];
    float* out = (float*)d_out;

    dim3 g1(O3_ / 64, N_ / 64, B_);   // 24 x 16 x 32
    qkv_kernel<<<g1, 256>>>(x, qkv_w, h_pos, w_pos);

    dim3 g2(N_ / 128, BP_);           // 8 x 256
    attn_kernel<<<g2, 128>>>(out);
}

// round 2
// speedup vs baseline: 1.7100x; 1.7100x over previous
#include <cuda_runtime.h>
#include <cuda_bf16.h>
#include <cstdint>

#define B_   32
#define CH_  512
#define N_   1024
#define D_   64
#define P_   8
#define BP_  256
#define O3_  1536

// Scratch: q, k' (=k + rel-pos), v in [b, p, n, d] layout.
__device__ float g_q[(size_t)BP_ * N_ * D_];
__device__ float g_k[(size_t)BP_ * N_ * D_];
__device__ float g_v[(size_t)BP_ * N_ * D_];

__device__ __forceinline__ uint32_t f2t(float x) {
    uint32_t u;
    asm("cvt.rna.tf32.f32 %0, %1;" : "=r"(u) : "f"(x));
    return u;
}

__device__ __forceinline__ void mma8(float* c,
                                     uint32_t a0, uint32_t a1, uint32_t a2, uint32_t a3,
                                     uint32_t b0, uint32_t b1) {
    asm("mma.sync.aligned.m16n8k8.row.col.f32.tf32.tf32.f32 "
        "{%0,%1,%2,%3}, {%4,%5,%6,%7}, {%8,%9}, {%0,%1,%2,%3};"
        : "+f"(c[0]), "+f"(c[1]), "+f"(c[2]), "+f"(c[3])
        : "r"(a0), "r"(a1), "r"(a2), "r"(a3), "r"(b0), "r"(b1));
}

// ---------------------------------------------------------------------------
// Kernel 1: QKV projection, split-tf32 (3x) tensor-core GEMM.
// Block tile 128(o) x 128(n), 8 warps of 32(o) x 64(n). K-step 32.
// ---------------------------------------------------------------------------
__global__ __launch_bounds__(256) void qkv_kernel(
    const float* __restrict__ x,      // [B, 512, 1024]
    const float* __restrict__ w,      // [1536, 512]
    const float* __restrict__ h_pos,  // [32, 1, 512]
    const float* __restrict__ w_pos)  // [1, 32, 512]
{
    extern __shared__ float sm[];
    float* Ah = sm;                 // [32][132]  (k, o) transposed
    float* Al = Ah + 32 * 132;
    float* Bh = Al + 32 * 132;      // [32][132]  (k, n)
    float* Bl = Bh + 32 * 132;
    float* Cs = sm;                 // reuse: [128][132] (n, o)

    const int tid  = threadIdx.x;
    const int lane = tid & 31;
    const int warp = tid >> 5;
    const int grp  = lane >> 2;
    const int t4   = lane & 3;
    const int ow   = (warp & 3) * 32;
    const int nw   = (warp >> 2) * 64;
    const int o0   = blockIdx.x * 128;
    const int n0   = blockIdx.y * 128;
    const int b    = blockIdx.z;

    float c[2][8][4];
#pragma unroll
    for (int m = 0; m < 2; m++)
#pragma unroll
        for (int nt = 0; nt < 8; nt++)
#pragma unroll
            for (int j = 0; j < 4; j++) c[m][nt][j] = 0.f;

    const size_t xbase = (size_t)b * CH_ * N_;

    for (int t = 0; t < 16; t++) {
        const int c0 = t * 32;
        __syncthreads();
        // Load W tile 128o x 32c, store transposed hi/lo
#pragma unroll
        for (int i = 0; i < 4; i++) {
            const int fid = tid + i * 256;
            const int ol  = fid >> 3;
            const int cs  = (fid & 7) * 4;
            float4 wv = *(const float4*)&w[(size_t)(o0 + ol) * CH_ + c0 + cs];
            float vv[4] = {wv.x, wv.y, wv.z, wv.w};
#pragma unroll
            for (int u = 0; u < 4; u++) {
                uint32_t hi = f2t(vv[u]);
                float hif = __uint_as_float(hi);
                Ah[(cs + u) * 132 + ol] = hif;
                Al[(cs + u) * 132 + ol] = __uint_as_float(f2t(vv[u] - hif));
            }
        }
        // Load X tile 32c x 128n hi/lo
#pragma unroll
        for (int i = 0; i < 4; i++) {
            const int fid = tid + i * 256;
            const int cl  = fid >> 5;
            const int ns  = (fid & 31) * 4;
            float4 xv = *(const float4*)&x[xbase + (size_t)(c0 + cl) * N_ + n0 + ns];
            float vv[4] = {xv.x, xv.y, xv.z, xv.w};
#pragma unroll
            for (int u = 0; u < 4; u++) {
                uint32_t hi = f2t(vv[u]);
                float hif = __uint_as_float(hi);
                Bh[cl * 132 + ns + u] = hif;
                Bl[cl * 132 + ns + u] = __uint_as_float(f2t(vv[u] - hif));
            }
        }
        __syncthreads();

#pragma unroll
        for (int ks = 0; ks < 4; ks++) {
            const int k0 = ks * 8;
            uint32_t bh[8][2], bl[8][2];
#pragma unroll
            for (int nt = 0; nt < 8; nt++) {
                const int nn = nw + nt * 8 + grp;
                bh[nt][0] = __float_as_uint(Bh[(k0 + t4) * 132 + nn]);
                bh[nt][1] = __float_as_uint(Bh[(k0 + t4 + 4) * 132 + nn]);
                bl[nt][0] = __float_as_uint(Bl[(k0 + t4) * 132 + nn]);
                bl[nt][1] = __float_as_uint(Bl[(k0 + t4 + 4) * 132 + nn]);
            }
#pragma unroll
            for (int m = 0; m < 2; m++) {
                const int ob = ow + m * 16;
                uint32_t ah0 = __float_as_uint(Ah[(k0 + t4) * 132 + ob + grp]);
                uint32_t ah1 = __float_as_uint(Ah[(k0 + t4) * 132 + ob + grp + 8]);
                uint32_t ah2 = __float_as_uint(Ah[(k0 + t4 + 4) * 132 + ob + grp]);
                uint32_t ah3 = __float_as_uint(Ah[(k0 + t4 + 4) * 132 + ob + grp + 8]);
                uint32_t al0 = __float_as_uint(Al[(k0 + t4) * 132 + ob + grp]);
                uint32_t al1 = __float_as_uint(Al[(k0 + t4) * 132 + ob + grp + 8]);
                uint32_t al2 = __float_as_uint(Al[(k0 + t4 + 4) * 132 + ob + grp]);
                uint32_t al3 = __float_as_uint(Al[(k0 + t4 + 4) * 132 + ob + grp + 8]);
#pragma unroll
                for (int nt = 0; nt < 8; nt++) {
                    mma8(c[m][nt], ah0, ah1, ah2, ah3, bh[nt][0], bh[nt][1]);
                    mma8(c[m][nt], ah0, ah1, ah2, ah3, bl[nt][0], bl[nt][1]);
                    mma8(c[m][nt], al0, al1, al2, al3, bh[nt][0], bh[nt][1]);
                }
            }
        }
    }

    // Epilogue: C frags -> smem [n][o] -> coalesced scatter into g_q/g_k/g_v.
    __syncthreads();
#pragma unroll
    for (int m = 0; m < 2; m++)
#pragma unroll
        for (int nt = 0; nt < 8; nt++) {
            const int nn = nw + nt * 8 + 2 * t4;
            const int oo = ow + m * 16 + grp;
            Cs[(nn + 0) * 132 + oo]     = c[m][nt][0];
            Cs[(nn + 1) * 132 + oo]     = c[m][nt][1];
            Cs[(nn + 0) * 132 + oo + 8] = c[m][nt][2];
            Cs[(nn + 1) * 132 + oo + 8] = c[m][nt][3];
        }
    __syncthreads();

#pragma unroll
    for (int j = 0; j < 16; j++) {
        const int fid = tid + j * 256;
        const int nl  = fid >> 5;
        const int os  = (fid & 31) * 4;
        float4 v4 = *(float4*)&Cs[nl * 132 + os];
        const int o  = o0 + os;
        const int s  = o >> 9;
        const int ch = o & 511;
        const int p  = ch >> 6;
        const int dd = ch & 63;
        const int n  = n0 + nl;
        if (s == 1) {
            const int hh = n >> 5, ww = n & 31;
            float4 hp = *(const float4*)&h_pos[hh * CH_ + ch];
            float4 wp = *(const float4*)&w_pos[ww * CH_ + ch];
            v4.x += hp.x + wp.x; v4.y += hp.y + wp.y;
            v4.z += hp.z + wp.z; v4.w += hp.w + wp.w;
        }
        float* dst = (s == 0) ? g_q : (s == 1) ? g_k : g_v;
        *(float4*)&dst[((size_t)(b * P_ + p) * N_ + n) * D_ + dd] = v4;
    }
}

// ---------------------------------------------------------------------------
// Kernel 2: flash attention on tensor cores.
// Block = 256 thr (8 warps) = 128 q rows; warp owns 16 q rows.
// S = Q*K'^T via split-tf32 (3 mmas); PV single tf32 (RNA).
// ---------------------------------------------------------------------------
__global__ __launch_bounds__(256) void attn_kernel(float* __restrict__ out)
{
    extern __shared__ float sm[];
    float* Kh = sm;                  // [64][68]  (key, d) hi
    float* Kl = Kh + 64 * 68;        // lo
    float* Vt = Kl + 64 * 68;        // [64][68]  (d, key) tf32
    float* Ps = Vt + 64 * 68;        // per-warp [16][68]

    const int tid  = threadIdx.x;
    const int lane = tid & 31;
    const int warp = tid >> 5;
    const int grp  = lane >> 2;
    const int t4   = lane & 3;
    const int bp   = blockIdx.y;
    const int q0   = blockIdx.x * 128 + warp * 16;
    float* Pw = Ps + warp * (16 * 68);

    // Q fragments (hi/lo) resident in registers
    uint32_t qh[8][4], ql[8][4];
    {
        const float* qp = g_q + ((size_t)bp * N_ + q0) * D_;
#pragma unroll
        for (int ks = 0; ks < 8; ks++) {
            float f0 = qp[grp * D_ + ks * 8 + t4];
            float f1 = qp[(grp + 8) * D_ + ks * 8 + t4];
            float f2 = qp[grp * D_ + ks * 8 + t4 + 4];
            float f3 = qp[(grp + 8) * D_ + ks * 8 + t4 + 4];
            qh[ks][0] = f2t(f0); ql[ks][0] = f2t(f0 - __uint_as_float(qh[ks][0]));
            qh[ks][1] = f2t(f1); ql[ks][1] = f2t(f1 - __uint_as_float(qh[ks][1]));
            qh[ks][2] = f2t(f2); ql[ks][2] = f2t(f2 - __uint_as_float(qh[ks][2]));
            qh[ks][3] = f2t(f3); ql[ks][3] = f2t(f3 - __uint_as_float(qh[ks][3]));
        }
    }

    float o[8][4];
#pragma unroll
    for (int nt = 0; nt < 8; nt++)
#pragma unroll
        for (int j = 0; j < 4; j++) o[nt][j] = 0.f;
    float m0 = -1e30f, m1 = -1e30f, l0 = 0.f, l1 = 0.f;

    for (int kt = 0; kt < 16; kt++) {
        __syncthreads();
        {
            const float* kg = g_k + ((size_t)bp * N_ + kt * 64) * D_;
            const float* vg = g_v + ((size_t)bp * N_ + kt * 64) * D_;
#pragma unroll
            for (int i = 0; i < 4; i++) {
                const int fid = tid + i * 256;
                const int key = fid >> 4;
                const int ds  = (fid & 15) * 4;
                float4 kv = *(const float4*)&kg[key * D_ + ds];
                float kk[4] = {kv.x, kv.y, kv.z, kv.w};
#pragma unroll
                for (int u = 0; u < 4; u++) {
                    uint32_t hi = f2t(kk[u]);
                    float hif = __uint_as_float(hi);
                    Kh[key * 68 + ds + u] = hif;
                    Kl[key * 68 + ds + u] = __uint_as_float(f2t(kk[u] - hif));
                }
                float4 vv = *(const float4*)&vg[key * D_ + ds];
                Vt[(ds + 0) * 68 + key] = __uint_as_float(f2t(vv.x));
                Vt[(ds + 1) * 68 + key] = __uint_as_float(f2t(vv.y));
                Vt[(ds + 2) * 68 + key] = __uint_as_float(f2t(vv.z));
                Vt[(ds + 3) * 68 + key] = __uint_as_float(f2t(vv.w));
            }
        }
        __syncthreads();

        // S = Q * K'^T  (split-tf32)
        float s[8][4];
#pragma unroll
        for (int nt = 0; nt < 8; nt++) {
            s[nt][0] = s[nt][1] = s[nt][2] = s[nt][3] = 0.f;
            const int key = nt * 8 + grp;
#pragma unroll
            for (int ks = 0; ks < 8; ks++) {
                uint32_t b0h = __float_as_uint(Kh[key * 68 + ks * 8 + t4]);
                uint32_t b1h = __float_as_uint(Kh[key * 68 + ks * 8 + t4 + 4]);
                uint32_t b0l = __float_as_uint(Kl[key * 68 + ks * 8 + t4]);
                uint32_t b1l = __float_as_uint(Kl[key * 68 + ks * 8 + t4 + 4]);
                mma8(s[nt], qh[ks][0], qh[ks][1], qh[ks][2], qh[ks][3], b0h, b1h);
                mma8(s[nt], qh[ks][0], qh[ks][1], qh[ks][2], qh[ks][3], b0l, b1l);
                mma8(s[nt], ql[ks][0], ql[ks][1], ql[ks][2], ql[ks][3], b0h, b1h);
            }
        }

        // online softmax (rows grp and grp+8)
        float mx0 = m0, mx1 = m1;
#pragma unroll
        for (int nt = 0; nt < 8; nt++) {
            mx0 = fmaxf(mx0, fmaxf(s[nt][0], s[nt][1]));
            mx1 = fmaxf(mx1, fmaxf(s[nt][2], s[nt][3]));
        }
        mx0 = fmaxf(mx0, __shfl_xor_sync(0xffffffffu, mx0, 1));
        mx0 = fmaxf(mx0, __shfl_xor_sync(0xffffffffu, mx0, 2));
        mx1 = fmaxf(mx1, __shfl_xor_sync(0xffffffffu, mx1, 1));
        mx1 = fmaxf(mx1, __shfl_xor_sync(0xffffffffu, mx1, 2));
        const float a0 = __expf(m0 - mx0), a1 = __expf(m1 - mx1);
        m0 = mx0; m1 = mx1;
        l0 *= a0; l1 *= a1;
        float ls0 = 0.f, ls1 = 0.f;
#pragma unroll
        for (int nt = 0; nt < 8; nt++) {
            o[nt][0] *= a0; o[nt][1] *= a0; o[nt][2] *= a1; o[nt][3] *= a1;
            s[nt][0] = __expf(s[nt][0] - m0); ls0 += s[nt][0];
            s[nt][1] = __expf(s[nt][1] - m0); ls0 += s[nt][1];
            s[nt][2] = __expf(s[nt][2] - m1); ls1 += s[nt][2];
            s[nt][3] = __expf(s[nt][3] - m1); ls1 += s[nt][3];
        }
        l0 += ls0; l1 += ls1;

        // P -> smem (tf32), re-fragment as A operand
#pragma unroll
        for (int nt = 0; nt < 8; nt++) {
            const int cc = nt * 8 + 2 * t4;
            Pw[grp * 68 + cc]           = __uint_as_float(f2t(s[nt][0]));
            Pw[grp * 68 + cc + 1]       = __uint_as_float(f2t(s[nt][1]));
            Pw[(grp + 8) * 68 + cc]     = __uint_as_float(f2t(s[nt][2]));
            Pw[(grp + 8) * 68 + cc + 1] = __uint_as_float(f2t(s[nt][3]));
        }
        __syncwarp();
        uint32_t pa[8][4];
#pragma unroll
        for (int ks = 0; ks < 8; ks++) {
            pa[ks][0] = __float_as_uint(Pw[grp * 68 + ks * 8 + t4]);
            pa[ks][1] = __float_as_uint(Pw[(grp + 8) * 68 + ks * 8 + t4]);
            pa[ks][2] = __float_as_uint(Pw[grp * 68 + ks * 8 + t4 + 4]);
            pa[ks][3] = __float_as_uint(Pw[(grp + 8) * 68 + ks * 8 + t4 + 4]);
        }
        // O += P * V
#pragma unroll
        for (int nt = 0; nt < 8; nt++) {
            const int dd = nt * 8 + grp;
#pragma unroll
            for (int ks = 0; ks < 8; ks++) {
                uint32_t b0 = __float_as_uint(Vt[dd * 68 + ks * 8 + t4]);
                uint32_t b1 = __float_as_uint(Vt[dd * 68 + ks * 8 + t4 + 4]);
                mma8(o[nt], pa[ks][0], pa[ks][1], pa[ks][2], pa[ks][3], b0, b1);
            }
        }
    }

    // finalize l across quad, write out via per-warp smem transpose
    l0 += __shfl_xor_sync(0xffffffffu, l0, 1);
    l0 += __shfl_xor_sync(0xffffffffu, l0, 2);
    l1 += __shfl_xor_sync(0xffffffffu, l1, 1);
    l1 += __shfl_xor_sync(0xffffffffu, l1, 2);
    const float i0 = 1.f / l0, i1 = 1.f / l1;

    __syncwarp();
#pragma unroll
    for (int nt = 0; nt < 8; nt++) {
        const int cc = nt * 8 + 2 * t4;
        Pw[grp * 68 + cc]           = o[nt][0] * i0;
        Pw[grp * 68 + cc + 1]       = o[nt][1] * i0;
        Pw[(grp + 8) * 68 + cc]     = o[nt][2] * i1;
        Pw[(grp + 8) * 68 + cc + 1] = o[nt][3] * i1;
    }
    __syncwarp();

    const int b = bp >> 3, p = bp & 7;
#pragma unroll
    for (int r = 0; r < 2; r++) {
        const int d = lane * 2 + r;
        float vals[16];
#pragma unroll
        for (int q = 0; q < 16; q++) vals[q] = Pw[q * 68 + d];
        float* ob = out + ((size_t)b * CH_ + p * D_ + d) * N_ + q0;
#pragma unroll
        for (int u = 0; u < 4; u++) {
            float4 v4 = {vals[u * 4], vals[u * 4 + 1], vals[u * 4 + 2], vals[u * 4 + 3]};
            *(float4*)&ob[u * 4] = v4;
        }
    }
}

extern "C" void kernel_launch(void* const* d_in, const int* in_sizes, int n_in,
                              void* d_out, int out_size)
{
    const float* x     = (const float*)d_in[0];
    const float* qkv_w = (const float*)d_in[1];
    const float* h_pos = (const float*)d_in[2];
    const float* w_pos = (const float*)d_in[3];
    float* out = (float*)d_out;

    const int smem1 = 4 * 32 * 132 * sizeof(float);                 // 67,584
    const int smem2 = (3 * 64 * 68 + 8 * 16 * 68) * sizeof(float);  // 87,040
    cudaFuncSetAttribute(qkv_kernel, cudaFuncAttributeMaxDynamicSharedMemorySize, smem1);
    cudaFuncSetAttribute(attn_kernel, cudaFuncAttributeMaxDynamicSharedMemorySize, smem2);

    dim3 g1(O3_ / 128, N_ / 128, B_);   // 12 x 8 x 32
    qkv_kernel<<<g1, 256, smem1>>>(x, qkv_w, h_pos, w_pos);

    dim3 g2(N_ / 128, BP_);             // 8 x 256
    attn_kernel<<<g2, 256, smem2>>>(out);
}

// round 3
// speedup vs baseline: 3.1126x; 1.8202x over previous
#include <cuda_runtime.h>
#include <cuda_bf16.h>
#include <cstdint>

#define B_   32
#define CH_  512
#define N_   1024
#define D_   64
#define P_   8
#define BP_  256
#define O3_  1536

// Split-bf16 scratch written by QKV kernel, consumed by attention kernel.
// q, k' (=k+relpos): [bp][n][d];  v: pre-transposed [bp][d][n].
__device__ __nv_bfloat16 g_qh[(size_t)BP_ * N_ * D_];
__device__ __nv_bfloat16 g_ql[(size_t)BP_ * N_ * D_];
__device__ __nv_bfloat16 g_kh[(size_t)BP_ * N_ * D_];
__device__ __nv_bfloat16 g_kl[(size_t)BP_ * N_ * D_];
__device__ __nv_bfloat16 g_vth[(size_t)BP_ * D_ * N_];
__device__ __nv_bfloat16 g_vtl[(size_t)BP_ * D_ * N_];

__device__ __forceinline__ uint32_t pack2(float lo, float hi) {
    uint32_t r;
    asm("cvt.rn.bf16x2.f32 %0, %1, %2;" : "=r"(r) : "f"(hi), "f"(lo));
    return r;
}
// split x0,x1 into bf16 hi pair + bf16 residual pair
__device__ __forceinline__ void split2(float x0, float x1, uint32_t& hi, uint32_t& lo) {
    float h0 = __bfloat162float(__float2bfloat16(x0));
    float h1 = __bfloat162float(__float2bfloat16(x1));
    hi = pack2(h0, h1);
    lo = pack2(x0 - h0, x1 - h1);
}

__device__ __forceinline__ void mma16(float* c, const uint32_t* a, uint32_t b0, uint32_t b1) {
    asm("mma.sync.aligned.m16n8k16.row.col.f32.bf16.bf16.f32 "
        "{%0,%1,%2,%3}, {%4,%5,%6,%7}, {%8,%9}, {%0,%1,%2,%3};"
        : "+f"(c[0]), "+f"(c[1]), "+f"(c[2]), "+f"(c[3])
        : "r"(a[0]), "r"(a[1]), "r"(a[2]), "r"(a[3]), "r"(b0), "r"(b1));
}

// ---------------------------------------------------------------------------
// Kernel 1: QKV projection, split-bf16 m16n8k16 GEMM.
// C[o][n] = sum_c W[o][c] X[c][n].  Block 128(o) x 128(n), 8 warps 32x64.
// W tile natural [o][c] (A row-major); X tile natural [c][n], B-frags built
// from two u16 LDS + pack.  Epilogue emits split-bf16 scratch (V transposed,
// stored directly from fragments).
// ---------------------------------------------------------------------------
__global__ __launch_bounds__(256, 2) void qkv_kernel(
    const float* __restrict__ x,      // [B, 512, 1024]
    const float* __restrict__ w,      // [1536, 512]
    const float* __restrict__ h_pos,  // [32, 1, 512]
    const float* __restrict__ w_pos)  // [1, 32, 512]
{
    extern __shared__ char smraw[];
    __nv_bfloat16* Wh = (__nv_bfloat16*)smraw;            // [128][36]
    __nv_bfloat16* Wl = Wh + 128 * 36;
    unsigned short* Xh = (unsigned short*)(Wl + 128 * 36); // [32][136]
    unsigned short* Xl = Xh + 32 * 136;
    float* Cs = (float*)smraw;                             // epilogue reuse [128][132]

    const int tid  = threadIdx.x;
    const int lane = tid & 31;
    const int warp = tid >> 5;
    const int grp  = lane >> 2;
    const int t4   = lane & 3;
    const int ow   = (warp & 3) * 32;
    const int nw   = (warp >> 2) * 64;
    const int o0   = blockIdx.x * 128;
    const int n0   = blockIdx.y * 128;
    const int b    = blockIdx.z;
    const size_t xbase = (size_t)b * CH_ * N_;

    float acc[2][8][4];
#pragma unroll
    for (int m = 0; m < 2; m++)
#pragma unroll
        for (int nt = 0; nt < 8; nt++)
#pragma unroll
            for (int j = 0; j < 4; j++) acc[m][nt][j] = 0.f;

    for (int t = 0; t < 16; t++) {
        const int c0 = t * 32;
        __syncthreads();
        // W tile: 128 o x 32 c  (1024 float4)
#pragma unroll
        for (int i = 0; i < 4; i++) {
            const int fid = tid + i * 256;
            const int ol  = fid >> 3;
            const int cs  = (fid & 7) * 4;
            float4 wv = *(const float4*)&w[(size_t)(o0 + ol) * CH_ + c0 + cs];
            uint32_t h0, l0, h1, l1;
            split2(wv.x, wv.y, h0, l0);
            split2(wv.z, wv.w, h1, l1);
            *(uint32_t*)(Wh + ol * 36 + cs)     = h0;
            *(uint32_t*)(Wh + ol * 36 + cs + 2) = h1;
            *(uint32_t*)(Wl + ol * 36 + cs)     = l0;
            *(uint32_t*)(Wl + ol * 36 + cs + 2) = l1;
        }
        // X tile: 32 c x 128 n  (1024 float4)
#pragma unroll
        for (int i = 0; i < 4; i++) {
            const int fid = tid + i * 256;
            const int cl  = fid >> 5;
            const int ns  = (fid & 31) * 4;
            float4 xv = *(const float4*)&x[xbase + (size_t)(c0 + cl) * N_ + n0 + ns];
            uint32_t h0, l0, h1, l1;
            split2(xv.x, xv.y, h0, l0);
            split2(xv.z, xv.w, h1, l1);
            *(uint32_t*)(Xh + cl * 136 + ns)     = h0;
            *(uint32_t*)(Xh + cl * 136 + ns + 2) = h1;
            *(uint32_t*)(Xl + cl * 136 + ns)     = l0;
            *(uint32_t*)(Xl + cl * 136 + ns + 2) = l1;
        }
        __syncthreads();

#pragma unroll
        for (int kc = 0; kc < 2; kc++) {
            uint32_t ah[2][4], al[2][4];
#pragma unroll
            for (int m = 0; m < 2; m++) {
                const int base = (ow + m * 16 + grp) * 36 + kc * 16 + 2 * t4;
                ah[m][0] = *(const uint32_t*)(Wh + base);
                ah[m][1] = *(const uint32_t*)(Wh + base + 8 * 36);
                ah[m][2] = *(const uint32_t*)(Wh + base + 8);
                ah[m][3] = *(const uint32_t*)(Wh + base + 8 * 36 + 8);
                al[m][0] = *(const uint32_t*)(Wl + base);
                al[m][1] = *(const uint32_t*)(Wl + base + 8 * 36);
                al[m][2] = *(const uint32_t*)(Wl + base + 8);
                al[m][3] = *(const uint32_t*)(Wl + base + 8 * 36 + 8);
            }
#pragma unroll
            for (int nt = 0; nt < 8; nt++) {
                const int n = nw + nt * 8 + grp;
                const int c = kc * 16 + 2 * t4;
                uint32_t b0h = (uint32_t)Xh[c * 136 + n]       | ((uint32_t)Xh[(c + 1) * 136 + n] << 16);
                uint32_t b1h = (uint32_t)Xh[(c + 8) * 136 + n] | ((uint32_t)Xh[(c + 9) * 136 + n] << 16);
                uint32_t b0l = (uint32_t)Xl[c * 136 + n]       | ((uint32_t)Xl[(c + 1) * 136 + n] << 16);
                uint32_t b1l = (uint32_t)Xl[(c + 8) * 136 + n] | ((uint32_t)Xl[(c + 9) * 136 + n] << 16);
#pragma unroll
                for (int m = 0; m < 2; m++) {
                    mma16(acc[m][nt], ah[m], b0h, b1h);
                    mma16(acc[m][nt], ah[m], b0l, b1l);
                    mma16(acc[m][nt], al[m], b0h, b1h);
                }
            }
        }
    }

    const int bv = b;  // batch
    if (o0 >= 1024) {
        // V blocks: store transposed, straight from fragments (consecutive-n pairs).
#pragma unroll
        for (int m = 0; m < 2; m++) {
            const int ch = (o0 - 1024) + ow + m * 16 + grp;
            const int p  = ch >> 6;
#pragma unroll
            for (int nt = 0; nt < 8; nt++) {
                const int n = n0 + nw + nt * 8 + 2 * t4;
                uint32_t h, l;
                // row ch (dd = ch&63)
                split2(acc[m][nt][0], acc[m][nt][1], h, l);
                size_t idx = ((size_t)(bv * P_ + p) * D_ + (ch & 63)) * N_ + n;
                *(uint32_t*)&g_vth[idx] = h;
                *(uint32_t*)&g_vtl[idx] = l;
                // row ch+8
                split2(acc[m][nt][2], acc[m][nt][3], h, l);
                idx = ((size_t)(bv * P_ + p) * D_ + ((ch + 8) & 63)) * N_ + n;
                *(uint32_t*)&g_vth[idx] = h;
                *(uint32_t*)&g_vtl[idx] = l;
            }
        }
        return;
    }

    // Q/K blocks: fragments -> Cs [n][132] -> coalesced split-bf16 stores.
    __syncthreads();
#pragma unroll
    for (int m = 0; m < 2; m++)
#pragma unroll
        for (int nt = 0; nt < 8; nt++) {
            const int nn = nw + nt * 8 + 2 * t4;
            const int oo = ow + m * 16 + grp;
            Cs[(nn + 0) * 132 + oo]     = acc[m][nt][0];
            Cs[(nn + 1) * 132 + oo]     = acc[m][nt][1];
            Cs[(nn + 0) * 132 + oo + 8] = acc[m][nt][2];
            Cs[(nn + 1) * 132 + oo + 8] = acc[m][nt][3];
        }
    __syncthreads();

    const bool isk = (o0 >= 512);
    __nv_bfloat16* dh = isk ? g_kh : g_qh;
    __nv_bfloat16* dl = isk ? g_kl : g_ql;
#pragma unroll
    for (int j = 0; j < 16; j++) {
        const int fid = tid + j * 256;
        const int nl  = fid >> 5;
        const int os  = (fid & 31) * 4;
        float4 v4 = *(float4*)&Cs[nl * 132 + os];
        const int o  = o0 + os;
        const int ch = o & 511;
        const int n  = n0 + nl;
        if (isk) {
            const int hh = n >> 5, ww = n & 31;
            float4 hp = *(const float4*)&h_pos[hh * CH_ + ch];
            float4 wp = *(const float4*)&w_pos[ww * CH_ + ch];
            v4.x += hp.x + wp.x; v4.y += hp.y + wp.y;
            v4.z += hp.z + wp.z; v4.w += hp.w + wp.w;
        }
        const int p = ch >> 6, dd = ch & 63;
        const size_t base = ((size_t)(bv * P_ + p) * N_ + n) * D_ + dd;
        uint32_t h0, l0, h1, l1;
        split2(v4.x, v4.y, h0, l0);
        split2(v4.z, v4.w, h1, l1);
        *(uint32_t*)&dh[base]     = h0;
        *(uint32_t*)&dh[base + 2] = h1;
        *(uint32_t*)&dl[base]     = l0;
        *(uint32_t*)&dl[base + 2] = l1;
    }
}

// ---------------------------------------------------------------------------
// Kernel 2: flash attention, split-bf16 m16n8k16.
// Block = 8 warps = 128 q rows; warp owns 16 rows. 64-key tiles.
// Q frags straight from gmem; K/V tiles plain uint4 copies; P re-fragmented
// in registers (C-layout == A-layout).
// ---------------------------------------------------------------------------
__global__ __launch_bounds__(256, 2) void attn_kernel(float* __restrict__ out)
{
    extern __shared__ char smraw[];
    __nv_bfloat16* Kh = (__nv_bfloat16*)smraw;   // [64 key][72 d]
    __nv_bfloat16* Kl = Kh + 64 * 72;
    __nv_bfloat16* Vh = Kl + 64 * 72;            // [64 d][72 key]
    __nv_bfloat16* Vl = Vh + 64 * 72;
    float* stage = (float*)(smraw + 4 * 64 * 72 * 2);  // 8 warps x [16][68]

    const int tid  = threadIdx.x;
    const int lane = tid & 31;
    const int warp = tid >> 5;
    const int grp  = lane >> 2;
    const int t4   = lane & 3;
    const int bp   = blockIdx.y;
    const int q0   = blockIdx.x * 128 + warp * 16;
    float* Pw = stage + warp * (16 * 68);

    // Q fragments straight from split-bf16 scratch
    uint32_t qh[4][4], ql[4][4];
    {
        const __nv_bfloat16* qhp = g_qh + ((size_t)bp * N_ + q0) * D_;
        const __nv_bfloat16* qlp = g_ql + ((size_t)bp * N_ + q0) * D_;
#pragma unroll
        for (int ks = 0; ks < 4; ks++) {
            const size_t r0 = (size_t)grp * D_ + ks * 16 + 2 * t4;
            qh[ks][0] = *(const uint32_t*)(qhp + r0);
            qh[ks][1] = *(const uint32_t*)(qhp + r0 + 8 * D_);
            qh[ks][2] = *(const uint32_t*)(qhp + r0 + 8);
            qh[ks][3] = *(const uint32_t*)(qhp + r0 + 8 * D_ + 8);
            ql[ks][0] = *(const uint32_t*)(qlp + r0);
            ql[ks][1] = *(const uint32_t*)(qlp + r0 + 8 * D_);
            ql[ks][2] = *(const uint32_t*)(qlp + r0 + 8);
            ql[ks][3] = *(const uint32_t*)(qlp + r0 + 8 * D_ + 8);
        }
    }

    float o[8][4];
#pragma unroll
    for (int nt = 0; nt < 8; nt++)
#pragma unroll
        for (int j = 0; j < 4; j++) o[nt][j] = 0.f;
    float m0 = -1e30f, m1 = -1e30f, l0 = 0.f, l1 = 0.f;

    for (int kt = 0; kt < 16; kt++) {
        __syncthreads();
        {
            const __nv_bfloat16* khp = g_kh + ((size_t)bp * N_ + kt * 64) * D_;
            const __nv_bfloat16* klp = g_kl + ((size_t)bp * N_ + kt * 64) * D_;
            const __nv_bfloat16* vhp = g_vth + (size_t)bp * D_ * N_ + kt * 64;
            const __nv_bfloat16* vlp = g_vtl + (size_t)bp * D_ * N_ + kt * 64;
#pragma unroll
            for (int i = 0; i < 2; i++) {
                const int idx = tid + i * 256;       // 0..511
                const int row = idx >> 3;
                const int j   = idx & 7;
                *(uint4*)(Kh + row * 72 + j * 8) = *(const uint4*)(khp + row * D_ + j * 8);
                *(uint4*)(Kl + row * 72 + j * 8) = *(const uint4*)(klp + row * D_ + j * 8);
                *(uint4*)(Vh + row * 72 + j * 8) = *(const uint4*)(vhp + (size_t)row * N_ + j * 8);
                *(uint4*)(Vl + row * 72 + j * 8) = *(const uint4*)(vlp + (size_t)row * N_ + j * 8);
            }
        }
        __syncthreads();

        // S = Q K'^T
        float s[8][4];
#pragma unroll
        for (int nt = 0; nt < 8; nt++) {
            s[nt][0] = s[nt][1] = s[nt][2] = s[nt][3] = 0.f;
            const int key = nt * 8 + grp;
#pragma unroll
            for (int ks = 0; ks < 4; ks++) {
                uint32_t b0h = *(const uint32_t*)(Kh + key * 72 + ks * 16 + 2 * t4);
                uint32_t b1h = *(const uint32_t*)(Kh + key * 72 + ks * 16 + 8 + 2 * t4);
                uint32_t b0l = *(const uint32_t*)(Kl + key * 72 + ks * 16 + 2 * t4);
                uint32_t b1l = *(const uint32_t*)(Kl + key * 72 + ks * 16 + 8 + 2 * t4);
                mma16(s[nt], qh[ks], b0h, b1h);
                mma16(s[nt], qh[ks], b0l, b1l);
                mma16(s[nt], ql[ks], b0h, b1h);
            }
        }

        // online softmax (rows grp, grp+8)
        float mx0 = m0, mx1 = m1;
#pragma unroll
        for (int nt = 0; nt < 8; nt++) {
            mx0 = fmaxf(mx0, fmaxf(s[nt][0], s[nt][1]));
            mx1 = fmaxf(mx1, fmaxf(s[nt][2], s[nt][3]));
        }
        mx0 = fmaxf(mx0, __shfl_xor_sync(0xffffffffu, mx0, 1));
        mx0 = fmaxf(mx0, __shfl_xor_sync(0xffffffffu, mx0, 2));
        mx1 = fmaxf(mx1, __shfl_xor_sync(0xffffffffu, mx1, 1));
        mx1 = fmaxf(mx1, __shfl_xor_sync(0xffffffffu, mx1, 2));
        const float a0 = __expf(m0 - mx0), a1 = __expf(m1 - mx1);
        m0 = mx0; m1 = mx1;
        l0 *= a0; l1 *= a1;
        float ls0 = 0.f, ls1 = 0.f;
#pragma unroll
        for (int nt = 0; nt < 8; nt++) {
            o[nt][0] *= a0; o[nt][1] *= a0; o[nt][2] *= a1; o[nt][3] *= a1;
            s[nt][0] = __expf(s[nt][0] - m0); ls0 += s[nt][0];
            s[nt][1] = __expf(s[nt][1] - m0); ls0 += s[nt][1];
            s[nt][2] = __expf(s[nt][2] - m1); ls1 += s[nt][2];
            s[nt][3] = __expf(s[nt][3] - m1); ls1 += s[nt][3];
        }
        l0 += ls0; l1 += ls1;

        // P fragments from C-layout registers (no smem round trip)
        uint32_t ph[4][4], pl[4][4];
#pragma unroll
        for (int ks = 0; ks < 4; ks++) {
            split2(s[2 * ks][0],     s[2 * ks][1],     ph[ks][0], pl[ks][0]);
            split2(s[2 * ks][2],     s[2 * ks][3],     ph[ks][1], pl[ks][1]);
            split2(s[2 * ks + 1][0], s[2 * ks + 1][1], ph[ks][2], pl[ks][2]);
            split2(s[2 * ks + 1][2], s[2 * ks + 1][3], ph[ks][3], pl[ks][3]);
        }

        // O += P V
#pragma unroll
        for (int nt = 0; nt < 8; nt++) {
            const int d = nt * 8 + grp;
#pragma unroll
            for (int ks = 0; ks < 4; ks++) {
                uint32_t b0h = *(const uint32_t*)(Vh + d * 72 + ks * 16 + 2 * t4);
                uint32_t b1h = *(const uint32_t*)(Vh + d * 72 + ks * 16 + 8 + 2 * t4);
                uint32_t b0l = *(const uint32_t*)(Vl + d * 72 + ks * 16 + 2 * t4);
                uint32_t b1l = *(const uint32_t*)(Vl + d * 72 + ks * 16 + 8 + 2 * t4);
                mma16(o[nt], ph[ks], b0h, b1h);
                mma16(o[nt], ph[ks], b0l, b1l);
                mma16(o[nt], pl[ks], b0h, b1h);
            }
        }
    }

    // normalize + write out via per-warp staging transpose
    l0 += __shfl_xor_sync(0xffffffffu, l0, 1);
    l0 += __shfl_xor_sync(0xffffffffu, l0, 2);
    l1 += __shfl_xor_sync(0xffffffffu, l1, 1);
    l1 += __shfl_xor_sync(0xffffffffu, l1, 2);
    const float i0 = 1.f / l0, i1 = 1.f / l1;

#pragma unroll
    for (int nt = 0; nt < 8; nt++) {
        const int cc = nt * 8 + 2 * t4;
        Pw[grp * 68 + cc]           = o[nt][0] * i0;
        Pw[grp * 68 + cc + 1]       = o[nt][1] * i0;
        Pw[(grp + 8) * 68 + cc]     = o[nt][2] * i1;
        Pw[(grp + 8) * 68 + cc + 1] = o[nt][3] * i1;
    }
    __syncwarp();

    const int b = bp >> 3, p = bp & 7;
#pragma unroll
    for (int r = 0; r < 2; r++) {
        const int d = lane * 2 + r;
        float vals[16];
#pragma unroll
        for (int q = 0; q < 16; q++) vals[q] = Pw[q * 68 + d];
        float* ob = out + ((size_t)b * CH_ + p * D_ + d) * N_ + q0;
#pragma unroll
        for (int u = 0; u < 4; u++) {
            float4 v4 = {vals[u * 4], vals[u * 4 + 1], vals[u * 4 + 2], vals[u * 4 + 3]};
            *(float4*)&ob[u * 4] = v4;
        }
    }
}

extern "C" void kernel_launch(void* const* d_in, const int* in_sizes, int n_in,
                              void* d_out, int out_size)
{
    const float* x     = (const float*)d_in[0];
    const float* qkv_w = (const float*)d_in[1];
    const float* h_pos = (const float*)d_in[2];
    const float* w_pos = (const float*)d_in[3];
    float* out = (float*)d_out;

    const int smem1 = 128 * 132 * sizeof(float);                       // 67,584 (>= mainloop tiles)
    const int smem2 = 4 * 64 * 72 * 2 + 8 * 16 * 68 * (int)sizeof(float);  // 71,680
    cudaFuncSetAttribute(qkv_kernel, cudaFuncAttributeMaxDynamicSharedMemorySize, smem1);
    cudaFuncSetAttribute(attn_kernel, cudaFuncAttributeMaxDynamicSharedMemorySize, smem2);

    dim3 g1(O3_ / 128, N_ / 128, B_);   // 12 x 8 x 32
    qkv_kernel<<<g1, 256, smem1>>>(x, qkv_w, h_pos, w_pos);

    dim3 g2(N_ / 128, BP_);             // 8 x 256
    attn_kernel<<<g2, 256, smem2>>>(out);
}

// round 4
// speedup vs baseline: 3.1171x; 1.0014x over previous
#include <cuda_runtime.h>
#include <cuda_bf16.h>
#include <cstdint>

#define B_   32
#define CH_  512
#define N_   1024
#define D_   64
#define P_   8
#define BP_  256
#define O3_  1536

// Split-bf16 scratch written by QKV kernel, consumed by attention kernel.
// q, k' (=k+relpos): [bp][n][d];  v: pre-transposed [bp][d][n].
__device__ __nv_bfloat16 g_qh[(size_t)BP_ * N_ * D_];
__device__ __nv_bfloat16 g_ql[(size_t)BP_ * N_ * D_];
__device__ __nv_bfloat16 g_kh[(size_t)BP_ * N_ * D_];
__device__ __nv_bfloat16 g_kl[(size_t)BP_ * N_ * D_];
__device__ __nv_bfloat16 g_vth[(size_t)BP_ * D_ * N_];
__device__ __nv_bfloat16 g_vtl[(size_t)BP_ * D_ * N_];

__device__ __forceinline__ uint32_t pack2(float lo, float hi) {
    uint32_t r;
    asm("cvt.rn.bf16x2.f32 %0, %1, %2;" : "=r"(r) : "f"(hi), "f"(lo));
    return r;
}
// split x0,x1 into bf16 hi pair + bf16 residual pair
__device__ __forceinline__ void split2(float x0, float x1, uint32_t& hi, uint32_t& lo) {
    float h0 = __bfloat162float(__float2bfloat16(x0));
    float h1 = __bfloat162float(__float2bfloat16(x1));
    hi = pack2(h0, h1);
    lo = pack2(x0 - h0, x1 - h1);
}

__device__ __forceinline__ void mma16(float* c, const uint32_t* a, uint32_t b0, uint32_t b1) {
    asm("mma.sync.aligned.m16n8k16.row.col.f32.bf16.bf16.f32 "
        "{%0,%1,%2,%3}, {%4,%5,%6,%7}, {%8,%9}, {%0,%1,%2,%3};"
        : "+f"(c[0]), "+f"(c[1]), "+f"(c[2]), "+f"(c[3])
        : "r"(a[0]), "r"(a[1]), "r"(a[2]), "r"(a[3]), "r"(b0), "r"(b1));
}

// ---------------------------------------------------------------------------
// Kernel 1: QKV projection, split-bf16 m16n8k16 GEMM.
// C[o][n] = sum_c W[o][c] X[c][n].  Block 128(o) x 128(n), 8 warps 32x64.
// W tile natural [o][c] (A row-major); X tile natural [c][n], B-frags built
// from two u16 LDS + pack.  Epilogue emits split-bf16 scratch (V transposed,
// stored directly from fragments).
// ---------------------------------------------------------------------------
__global__ __launch_bounds__(256, 2) void qkv_kernel(
    const float* __restrict__ x,      // [B, 512, 1024]
    const float* __restrict__ w,      // [1536, 512]
    const float* __restrict__ h_pos,  // [32, 1, 512]
    const float* __restrict__ w_pos)  // [1, 32, 512]
{
    extern __shared__ char smraw[];
    __nv_bfloat16* Wh = (__nv_bfloat16*)smraw;            // [128][36]
    __nv_bfloat16* Wl = Wh + 128 * 36;
    unsigned short* Xh = (unsigned short*)(Wl + 128 * 36); // [32][136]
    unsigned short* Xl = Xh + 32 * 136;
    float* Cs = (float*)smraw;                             // epilogue reuse [128][132]

    const int tid  = threadIdx.x;
    const int lane = tid & 31;
    const int warp = tid >> 5;
    const int grp  = lane >> 2;
    const int t4   = lane & 3;
    const int ow   = (warp & 3) * 32;
    const int nw   = (warp >> 2) * 64;
    const int o0   = blockIdx.x * 128;
    const int n0   = blockIdx.y * 128;
    const int b    = blockIdx.z;
    const size_t xbase = (size_t)b * CH_ * N_;

    float acc[2][8][4];
#pragma unroll
    for (int m = 0; m < 2; m++)
#pragma unroll
        for (int nt = 0; nt < 8; nt++)
#pragma unroll
            for (int j = 0; j < 4; j++) acc[m][nt][j] = 0.f;

    for (int t = 0; t < 16; t++) {
        const int c0 = t * 32;
        __syncthreads();
        // W tile: 128 o x 32 c  (1024 float4)
#pragma unroll
        for (int i = 0; i < 4; i++) {
            const int fid = tid + i * 256;
            const int ol  = fid >> 3;
            const int cs  = (fid & 7) * 4;
            float4 wv = *(const float4*)&w[(size_t)(o0 + ol) * CH_ + c0 + cs];
            uint32_t h0, l0, h1, l1;
            split2(wv.x, wv.y, h0, l0);
            split2(wv.z, wv.w, h1, l1);
            *(uint32_t*)(Wh + ol * 36 + cs)     = h0;
            *(uint32_t*)(Wh + ol * 36 + cs + 2) = h1;
            *(uint32_t*)(Wl + ol * 36 + cs)     = l0;
            *(uint32_t*)(Wl + ol * 36 + cs + 2) = l1;
        }
        // X tile: 32 c x 128 n  (1024 float4)
#pragma unroll
        for (int i = 0; i < 4; i++) {
            const int fid = tid + i * 256;
            const int cl  = fid >> 5;
            const int ns  = (fid & 31) * 4;
            float4 xv = *(const float4*)&x[xbase + (size_t)(c0 + cl) * N_ + n0 + ns];
            uint32_t h0, l0, h1, l1;
            split2(xv.x, xv.y, h0, l0);
            split2(xv.z, xv.w, h1, l1);
            *(uint32_t*)(Xh + cl * 136 + ns)     = h0;
            *(uint32_t*)(Xh + cl * 136 + ns + 2) = h1;
            *(uint32_t*)(Xl + cl * 136 + ns)     = l0;
            *(uint32_t*)(Xl + cl * 136 + ns + 2) = l1;
        }
        __syncthreads();

#pragma unroll
        for (int kc = 0; kc < 2; kc++) {
            uint32_t ah[2][4], al[2][4];
#pragma unroll
            for (int m = 0; m < 2; m++) {
                const int base = (ow + m * 16 + grp) * 36 + kc * 16 + 2 * t4;
                ah[m][0] = *(const uint32_t*)(Wh + base);
                ah[m][1] = *(const uint32_t*)(Wh + base + 8 * 36);
                ah[m][2] = *(const uint32_t*)(Wh + base + 8);
                ah[m][3] = *(const uint32_t*)(Wh + base + 8 * 36 + 8);
                al[m][0] = *(const uint32_t*)(Wl + base);
                al[m][1] = *(const uint32_t*)(Wl + base + 8 * 36);
                al[m][2] = *(const uint32_t*)(Wl + base + 8);
                al[m][3] = *(const uint32_t*)(Wl + base + 8 * 36 + 8);
            }
#pragma unroll
            for (int nt = 0; nt < 8; nt++) {
                const int n = nw + nt * 8 + grp;
                const int c = kc * 16 + 2 * t4;
                uint32_t b0h = (uint32_t)Xh[c * 136 + n]       | ((uint32_t)Xh[(c + 1) * 136 + n] << 16);
                uint32_t b1h = (uint32_t)Xh[(c + 8) * 136 + n] | ((uint32_t)Xh[(c + 9) * 136 + n] << 16);
                uint32_t b0l = (uint32_t)Xl[c * 136 + n]       | ((uint32_t)Xl[(c + 1) * 136 + n] << 16);
                uint32_t b1l = (uint32_t)Xl[(c + 8) * 136 + n] | ((uint32_t)Xl[(c + 9) * 136 + n] << 16);
#pragma unroll
                for (int m = 0; m < 2; m++) {
                    mma16(acc[m][nt], ah[m], b0h, b1h);
                    mma16(acc[m][nt], ah[m], b0l, b1l);
                    mma16(acc[m][nt], al[m], b0h, b1h);
                }
            }
        }
    }

    const int bv = b;  // batch
    if (o0 >= 1024) {
        // V blocks: store transposed, straight from fragments (consecutive-n pairs).
#pragma unroll
        for (int m = 0; m < 2; m++) {
            const int ch = (o0 - 1024) + ow + m * 16 + grp;
            const int p  = ch >> 6;
#pragma unroll
            for (int nt = 0; nt < 8; nt++) {
                const int n = n0 + nw + nt * 8 + 2 * t4;
                uint32_t h, l;
                // row ch (dd = ch&63)
                split2(acc[m][nt][0], acc[m][nt][1], h, l);
                size_t idx = ((size_t)(bv * P_ + p) * D_ + (ch & 63)) * N_ + n;
                *(uint32_t*)&g_vth[idx] = h;
                *(uint32_t*)&g_vtl[idx] = l;
                // row ch+8
                split2(acc[m][nt][2], acc[m][nt][3], h, l);
                idx = ((size_t)(bv * P_ + p) * D_ + ((ch + 8) & 63)) * N_ + n;
                *(uint32_t*)&g_vth[idx] = h;
                *(uint32_t*)&g_vtl[idx] = l;
            }
        }
        return;
    }

    // Q/K blocks: fragments -> Cs [n][132] -> coalesced split-bf16 stores.
    __syncthreads();
#pragma unroll
    for (int m = 0; m < 2; m++)
#pragma unroll
        for (int nt = 0; nt < 8; nt++) {
            const int nn = nw + nt * 8 + 2 * t4;
            const int oo = ow + m * 16 + grp;
            Cs[(nn + 0) * 132 + oo]     = acc[m][nt][0];
            Cs[(nn + 1) * 132 + oo]     = acc[m][nt][1];
            Cs[(nn + 0) * 132 + oo + 8] = acc[m][nt][2];
            Cs[(nn + 1) * 132 + oo + 8] = acc[m][nt][3];
        }
    __syncthreads();

    const bool isk = (o0 >= 512);
    __nv_bfloat16* dh = isk ? g_kh : g_qh;
    __nv_bfloat16* dl = isk ? g_kl : g_ql;
#pragma unroll
    for (int j = 0; j < 16; j++) {
        const int fid = tid + j * 256;
        const int nl  = fid >> 5;
        const int os  = (fid & 31) * 4;
        float4 v4 = *(float4*)&Cs[nl * 132 + os];
        const int o  = o0 + os;
        const int ch = o & 511;
        const int n  = n0 + nl;
        if (isk) {
            const int hh = n >> 5, ww = n & 31;
            float4 hp = *(const float4*)&h_pos[hh * CH_ + ch];
            float4 wp = *(const float4*)&w_pos[ww * CH_ + ch];
            v4.x += hp.x + wp.x; v4.y += hp.y + wp.y;
            v4.z += hp.z + wp.z; v4.w += hp.w + wp.w;
        }
        const int p = ch >> 6, dd = ch & 63;
        const size_t base = ((size_t)(bv * P_ + p) * N_ + n) * D_ + dd;
        uint32_t h0, l0, h1, l1;
        split2(v4.x, v4.y, h0, l0);
        split2(v4.z, v4.w, h1, l1);
        *(uint32_t*)&dh[base]     = h0;
        *(uint32_t*)&dh[base + 2] = h1;
        *(uint32_t*)&dl[base]     = l0;
        *(uint32_t*)&dl[base + 2] = l1;
    }
}

// ---------------------------------------------------------------------------
// Kernel 2: flash attention, split-bf16 m16n8k16.
// Block = 8 warps = 128 q rows; warp owns 16 rows. 64-key tiles.
// Q frags straight from gmem; K/V tiles plain uint4 copies; P re-fragmented
// in registers (C-layout == A-layout).
// ---------------------------------------------------------------------------
__global__ __launch_bounds__(256, 2) void attn_kernel(float* __restrict__ out)
{
    extern __shared__ char smraw[];
    __nv_bfloat16* Kh = (__nv_bfloat16*)smraw;   // [64 key][72 d]
    __nv_bfloat16* Kl = Kh + 64 * 72;
    __nv_bfloat16* Vh = Kl + 64 * 72;            // [64 d][72 key]
    __nv_bfloat16* Vl = Vh + 64 * 72;
    float* stage = (float*)(smraw + 4 * 64 * 72 * 2);  // 8 warps x [16][68]

    const int tid  = threadIdx.x;
    const int lane = tid & 31;
    const int warp = tid >> 5;
    const int grp  = lane >> 2;
    const int t4   = lane & 3;
    const int bp   = blockIdx.y;
    const int q0   = blockIdx.x * 128 + warp * 16;
    float* Pw = stage + warp * (16 * 68);

    // Q fragments straight from split-bf16 scratch
    uint32_t qh[4][4], ql[4][4];
    {
        const __nv_bfloat16* qhp = g_qh + ((size_t)bp * N_ + q0) * D_;
        const __nv_bfloat16* qlp = g_ql + ((size_t)bp * N_ + q0) * D_;
#pragma unroll
        for (int ks = 0; ks < 4; ks++) {
            const size_t r0 = (size_t)grp * D_ + ks * 16 + 2 * t4;
            qh[ks][0] = *(const uint32_t*)(qhp + r0);
            qh[ks][1] = *(const uint32_t*)(qhp + r0 + 8 * D_);
            qh[ks][2] = *(const uint32_t*)(qhp + r0 + 8);
            qh[ks][3] = *(const uint32_t*)(qhp + r0 + 8 * D_ + 8);
            ql[ks][0] = *(const uint32_t*)(qlp + r0);
            ql[ks][1] = *(const uint32_t*)(qlp + r0 + 8 * D_);
            ql[ks][2] = *(const uint32_t*)(qlp + r0 + 8);
            ql[ks][3] = *(const uint32_t*)(qlp + r0 + 8 * D_ + 8);
        }
    }

    float o[8][4];
#pragma unroll
    for (int nt = 0; nt < 8; nt++)
#pragma unroll
        for (int j = 0; j < 4; j++) o[nt][j] = 0.f;
    float m0 = -1e30f, m1 = -1e30f, l0 = 0.f, l1 = 0.f;

    for (int kt = 0; kt < 16; kt++) {
        __syncthreads();
        {
            const __nv_bfloat16* khp = g_kh + ((size_t)bp * N_ + kt * 64) * D_;
            const __nv_bfloat16* klp = g_kl + ((size_t)bp * N_ + kt * 64) * D_;
            const __nv_bfloat16* vhp = g_vth + (size_t)bp * D_ * N_ + kt * 64;
            const __nv_bfloat16* vlp = g_vtl + (size_t)bp * D_ * N_ + kt * 64;
#pragma unroll
            for (int i = 0; i < 2; i++) {
                const int idx = tid + i * 256;       // 0..511
                const int row = idx >> 3;
                const int j   = idx & 7;
                *(uint4*)(Kh + row * 72 + j * 8) = *(const uint4*)(khp + row * D_ + j * 8);
                *(uint4*)(Kl + row * 72 + j * 8) = *(const uint4*)(klp + row * D_ + j * 8);
                *(uint4*)(Vh + row * 72 + j * 8) = *(const uint4*)(vhp + (size_t)row * N_ + j * 8);
                *(uint4*)(Vl + row * 72 + j * 8) = *(const uint4*)(vlp + (size_t)row * N_ + j * 8);
            }
        }
        __syncthreads();

        // S = Q K'^T
        float s[8][4];
#pragma unroll
        for (int nt = 0; nt < 8; nt++) {
            s[nt][0] = s[nt][1] = s[nt][2] = s[nt][3] = 0.f;
            const int key = nt * 8 + grp;
#pragma unroll
            for (int ks = 0; ks < 4; ks++) {
                uint32_t b0h = *(const uint32_t*)(Kh + key * 72 + ks * 16 + 2 * t4);
                uint32_t b1h = *(const uint32_t*)(Kh + key * 72 + ks * 16 + 8 + 2 * t4);
                uint32_t b0l = *(const uint32_t*)(Kl + key * 72 + ks * 16 + 2 * t4);
                uint32_t b1l = *(const uint32_t*)(Kl + key * 72 + ks * 16 + 8 + 2 * t4);
                mma16(s[nt], qh[ks], b0h, b1h);
                mma16(s[nt], qh[ks], b0l, b1l);
                mma16(s[nt], ql[ks], b0h, b1h);
            }
        }

        // online softmax (rows grp, grp+8)
        float mx0 = m0, mx1 = m1;
#pragma unroll
        for (int nt = 0; nt < 8; nt++) {
            mx0 = fmaxf(mx0, fmaxf(s[nt][0], s[nt][1]));
            mx1 = fmaxf(mx1, fmaxf(s[nt][2], s[nt][3]));
        }
        mx0 = fmaxf(mx0, __shfl_xor_sync(0xffffffffu, mx0, 1));
        mx0 = fmaxf(mx0, __shfl_xor_sync(0xffffffffu, mx0, 2));
        mx1 = fmaxf(mx1, __shfl_xor_sync(0xffffffffu, mx1, 1));
        mx1 = fmaxf(mx1, __shfl_xor_sync(0xffffffffu, mx1, 2));
        const float a0 = __expf(m0 - mx0), a1 = __expf(m1 - mx1);
        m0 = mx0; m1 = mx1;
        l0 *= a0; l1 *= a1;
        float ls0 = 0.f, ls1 = 0.f;
#pragma unroll
        for (int nt = 0; nt < 8; nt++) {
            o[nt][0] *= a0; o[nt][1] *= a0; o[nt][2] *= a1; o[nt][3] *= a1;
            s[nt][0] = __expf(s[nt][0] - m0); ls0 += s[nt][0];
            s[nt][1] = __expf(s[nt][1] - m0); ls0 += s[nt][1];
            s[nt][2] = __expf(s[nt][2] - m1); ls1 += s[nt][2];
            s[nt][3] = __expf(s[nt][3] - m1); ls1 += s[nt][3];
        }
        l0 += ls0; l1 += ls1;

        // P fragments from C-layout registers (no smem round trip)
        uint32_t ph[4][4], pl[4][4];
#pragma unroll
        for (int ks = 0; ks < 4; ks++) {
            split2(s[2 * ks][0],     s[2 * ks][1],     ph[ks][0], pl[ks][0]);
            split2(s[2 * ks][2],     s[2 * ks][3],     ph[ks][1], pl[ks][1]);
            split2(s[2 * ks + 1][0], s[2 * ks + 1][1], ph[ks][2], pl[ks][2]);
            split2(s[2 * ks + 1][2], s[2 * ks + 1][3], ph[ks][3], pl[ks][3]);
        }

        // O += P V
#pragma unroll
        for (int nt = 0; nt < 8; nt++) {
            const int d = nt * 8 + grp;
#pragma unroll
            for (int ks = 0; ks < 4; ks++) {
                uint32_t b0h = *(const uint32_t*)(Vh + d * 72 + ks * 16 + 2 * t4);
                uint32_t b1h = *(const uint32_t*)(Vh + d * 72 + ks * 16 + 8 + 2 * t4);
                uint32_t b0l = *(const uint32_t*)(Vl + d * 72 + ks * 16 + 2 * t4);
                uint32_t b1l = *(const uint32_t*)(Vl + d * 72 + ks * 16 + 8 + 2 * t4);
                mma16(o[nt], ph[ks], b0h, b1h);
                mma16(o[nt], ph[ks], b0l, b1l);
                mma16(o[nt], pl[ks], b0h, b1h);
            }
        }
    }

    // normalize + write out via per-warp staging transpose
    l0 += __shfl_xor_sync(0xffffffffu, l0, 1);
    l0 += __shfl_xor_sync(0xffffffffu, l0, 2);
    l1 += __shfl_xor_sync(0xffffffffu, l1, 1);
    l1 += __shfl_xor_sync(0xffffffffu, l1, 2);
    const float i0 = 1.f / l0, i1 = 1.f / l1;

#pragma unroll
    for (int nt = 0; nt < 8; nt++) {
        const int cc = nt * 8 + 2 * t4;
        Pw[grp * 68 + cc]           = o[nt][0] * i0;
        Pw[grp * 68 + cc + 1]       = o[nt][1] * i0;
        Pw[(grp + 8) * 68 + cc]     = o[nt][2] * i1;
        Pw[(grp + 8) * 68 + cc + 1] = o[nt][3] * i1;
    }
    __syncwarp();

    const int b = bp >> 3, p = bp & 7;
#pragma unroll
    for (int r = 0; r < 2; r++) {
        const int d = lane * 2 + r;
        float vals[16];
#pragma unroll
        for (int q = 0; q < 16; q++) vals[q] = Pw[q * 68 + d];
        float* ob = out + ((size_t)b * CH_ + p * D_ + d) * N_ + q0;
#pragma unroll
        for (int u = 0; u < 4; u++) {
            float4 v4 = {vals[u * 4], vals[u * 4 + 1], vals[u * 4 + 2], vals[u * 4 + 3]};
            *(float4*)&ob[u * 4] = v4;
        }
    }
}

extern "C" void kernel_launch(void* const* d_in, const int* in_sizes, int n_in,
                              void* d_out, int out_size)
{
    const float* x     = (const float*)d_in[0];
    const float* qkv_w = (const float*)d_in[1];
    const float* h_pos = (const float*)d_in[2];
    const float* w_pos = (const float*)d_in[3];
    float* out = (float*)d_out;

    const int smem1 = 128 * 132 * sizeof(float);                       // 67,584 (>= mainloop tiles)
    const int smem2 = 4 * 64 * 72 * 2 + 8 * 16 * 68 * (int)sizeof(float);  // 71,680
    cudaFuncSetAttribute(qkv_kernel, cudaFuncAttributeMaxDynamicSharedMemorySize, smem1);
    cudaFuncSetAttribute(attn_kernel, cudaFuncAttributeMaxDynamicSharedMemorySize, smem2);

    dim3 g1(O3_ / 128, N_ / 128, B_);   // 12 x 8 x 32
    qkv_kernel<<<g1, 256, smem1>>>(x, qkv_w, h_pos, w_pos);

    dim3 g2(N_ / 128, BP_);             // 8 x 256
    attn_kernel<<<g2, 256, smem2>>>(out);
}